// round 1
// baseline (speedup 1.0000x reference)
#include <cuda_runtime.h>
#include <math.h>
#include <stdint.h>

// Problem constants (fixed by the benchmark shapes)
#define BB   4
#define NN   16384
#define CC   256
#define C3   768
#define TT   64        // categories
#define HH   8         // heads
#define DD   32        // head dim
#define GS   128       // group size
#define NG   128       // groups per batch (N/GS), no padding since N % GS == 0
#define NCH  128       // chunks per batch for counting sort
#define CHSZ 128       // tokens per chunk

// -------- scratch (device globals; no runtime allocation allowed) --------
__device__ int   g_tkid[BB * NN];
__device__ int   g_sortidx[BB * NN];
__device__ int   g_hist[BB * TT * NCH];          // [b][bin][chunk]
__device__ float g_y[(size_t)BB * NN * CC];      // 64 MB intermediate (pre-projection)

// ---------------- 1) per-token argmax over 64 categories ----------------
__global__ void k_argmax(const float* __restrict__ sim) {
    int idx = blockIdx.x * blockDim.x + threadIdx.x;
    if (idx >= BB * NN) return;
    const float4* p = (const float4*)(sim + (size_t)idx * TT);
    float best = -3.402823466e38f;
    int bi = 0;
#pragma unroll
    for (int i = 0; i < 16; i++) {
        float4 v = p[i];
        if (v.x > best) { best = v.x; bi = 4 * i + 0; }
        if (v.y > best) { best = v.y; bi = 4 * i + 1; }
        if (v.z > best) { best = v.z; bi = 4 * i + 2; }
        if (v.w > best) { best = v.w; bi = 4 * i + 3; }
    }
    g_tkid[idx] = bi;
}

// ---------------- 2a) per-(batch,chunk) key histogram ----------------
__global__ void k_hist() {
    __shared__ int h[TT];
    int ch = blockIdx.x;
    int b  = blockIdx.y;
    if (threadIdx.x < TT) h[threadIdx.x] = 0;
    __syncthreads();
    int key = g_tkid[b * NN + ch * CHSZ + threadIdx.x];
    atomicAdd(&h[key], 1);
    __syncthreads();
    if (threadIdx.x < TT)
        g_hist[(b * TT + threadIdx.x) * NCH + ch] = h[threadIdx.x];
}

// ---------------- 2b) exclusive scan over (bin-major, chunk-minor) ----------------
// One block per batch; 256 threads x 32 contiguous elements = 8192.
__global__ void k_scan() {
    __shared__ int tot[256];
    int b = blockIdx.x;
    int* base = g_hist + b * TT * NCH;
    int t = threadIdx.x;
    int v[32];
    int s = 0;
#pragma unroll
    for (int i = 0; i < 32; i++) { v[i] = base[t * 32 + i]; s += v[i]; }
    tot[t] = s;
    __syncthreads();
    if (t == 0) {
        int acc = 0;
        for (int i = 0; i < 256; i++) { int x = tot[i]; tot[i] = acc; acc += x; }
    }
    __syncthreads();
    int ex = tot[t];
#pragma unroll
    for (int i = 0; i < 32; i++) { int x = v[i]; base[t * 32 + i] = ex; ex += x; }
}

// ---------------- 2c) stable scatter (counting sort finish) ----------------
// One thread per (batch, chunk); processes its 128 tokens in index order -> stable.
__global__ void k_scatter() {
    int gid = blockIdx.x * blockDim.x + threadIdx.x;
    if (gid >= BB * NCH) return;
    int b  = gid / NCH;
    int ch = gid % NCH;
    int off[TT];
#pragma unroll
    for (int k = 0; k < TT; k++) off[k] = g_hist[(b * TT + k) * NCH + ch];
    const int* tk = g_tkid + b * NN + ch * CHSZ;
    int* so = g_sortidx + b * NN;
    for (int i = 0; i < CHSZ; i++) {
        int key = tk[i];
        so[off[key]++] = ch * CHSZ + i;
    }
}

// ---------------- 3) grouped attention, gather + inverse-scatter fused ----------------
// Block = one (b, g, h). 128 threads = one query row each.
// smem: K[128*32] + V[128*32] + S[128*129]  = 98816 B dynamic.
extern __shared__ float sm_att[];
__global__ void __launch_bounds__(128, 2)
k_attn(const float* __restrict__ qkv, const float* __restrict__ logit_scale) {
    float* Ks = sm_att;                 // 128 x 32
    float* Vs = sm_att + GS * DD;       // 128 x 32
    float* Ss = sm_att + 2 * GS * DD;   // 128 x 129 (padded rows, conflict-free)

    int g = blockIdx.x, h = blockIdx.y, b = blockIdx.z;
    int q = threadIdx.x;

    int tok = g_sortidx[b * NN + g * GS + q];
    size_t rowbase = (size_t)(b * NN + tok) * C3 + h * DD;

    float qr[DD];
    const float4* qp = (const float4*)(qkv + rowbase);
    const float4* kp = (const float4*)(qkv + rowbase + CC);
    const float4* vp = (const float4*)(qkv + rowbase + 2 * CC);
#pragma unroll
    for (int i = 0; i < 8; i++) {
        float4 x = qp[i];
        qr[4 * i + 0] = x.x; qr[4 * i + 1] = x.y; qr[4 * i + 2] = x.z; qr[4 * i + 3] = x.w;
        ((float4*)(Ks + q * DD))[i] = kp[i];
        ((float4*)(Vs + q * DD))[i] = vp[i];
    }
    float scale = expf(fminf(logit_scale[0], logf(100.0f)));
    __syncthreads();

    float* srow = Ss + q * (GS + 1);
    float m = -3.402823466e38f;
#pragma unroll 4
    for (int j = 0; j < GS; j++) {
        const float* kr = Ks + j * DD;
        float acc = 0.0f;
#pragma unroll
        for (int kk = 0; kk < DD; kk++) acc += qr[kk] * kr[kk];
        acc *= scale;
        srow[j] = acc;
        m = fmaxf(m, acc);
    }

    float sum = 0.0f;
#pragma unroll 4
    for (int j = 0; j < GS; j++) {
        float e = expf(srow[j] - m);
        srow[j] = e;
        sum += e;
    }
    float inv = 1.0f / sum;

    float acc[DD];
#pragma unroll
    for (int kk = 0; kk < DD; kk++) acc[kk] = 0.0f;
#pragma unroll 2
    for (int j = 0; j < GS; j++) {
        float w = srow[j];
        const float* vr = Vs + j * DD;
#pragma unroll
        for (int kk = 0; kk < DD; kk++) acc[kk] += w * vr[kk];
    }

    // write directly at ORIGINAL token position -> inverse permutation fused
    float* orow = g_y + (size_t)(b * NN + tok) * CC + h * DD;
#pragma unroll
    for (int i = 0; i < 8; i++) {
        float4 o;
        o.x = acc[4 * i + 0] * inv; o.y = acc[4 * i + 1] * inv;
        o.z = acc[4 * i + 2] * inv; o.w = acc[4 * i + 3] * inv;
        ((float4*)orow)[i] = o;
    }
}

// ---------------- 4) output projection: out = y @ W^T + bias ----------------
// M=65536, N=256, K=256. BM=BN=128, BK=16, 256 threads, 8x8 micro-tile.
#define PBM 128
#define PBN 128
#define PBK 16
__global__ void __launch_bounds__(256, 2)
k_proj(const float* __restrict__ W, const float* __restrict__ bias,
       float* __restrict__ out) {
    __shared__ float As[PBK][PBM];
    __shared__ float Bs[PBK][PBN];

    int tid = threadIdx.x;
    int row0 = blockIdx.x * PBM;
    int col0 = blockIdx.y * PBN;
    int tx = tid & 15, ty = tid >> 4;

    float acc[8][8];
#pragma unroll
    for (int r = 0; r < 8; r++)
#pragma unroll
        for (int c = 0; c < 8; c++) acc[r][c] = 0.0f;

    for (int k0 = 0; k0 < CC; k0 += PBK) {
#pragma unroll
        for (int l = 0; l < 2; l++) {
            int i  = tid * 2 + l;     // 0..511 -> 512 float4 per tile
            int mm = i >> 2;          // 0..127
            int kq = i & 3;           // 0..3
            float4 a = *(const float4*)(g_y + (size_t)(row0 + mm) * CC + k0 + kq * 4);
            As[kq * 4 + 0][mm] = a.x; As[kq * 4 + 1][mm] = a.y;
            As[kq * 4 + 2][mm] = a.z; As[kq * 4 + 3][mm] = a.w;
            float4 w = *(const float4*)(W + (size_t)(col0 + mm) * CC + k0 + kq * 4);
            Bs[kq * 4 + 0][mm] = w.x; Bs[kq * 4 + 1][mm] = w.y;
            Bs[kq * 4 + 2][mm] = w.z; Bs[kq * 4 + 3][mm] = w.w;
        }
        __syncthreads();
#pragma unroll
        for (int k = 0; k < PBK; k++) {
            float a[8], bb[8];
#pragma unroll
            for (int r = 0; r < 8; r++) a[r] = As[k][ty * 8 + r];
#pragma unroll
            for (int c = 0; c < 8; c++) bb[c] = Bs[k][tx * 8 + c];
#pragma unroll
            for (int r = 0; r < 8; r++)
#pragma unroll
                for (int c = 0; c < 8; c++) acc[r][c] += a[r] * bb[c];
        }
        __syncthreads();
    }

#pragma unroll
    for (int r = 0; r < 8; r++) {
        float* orow = out + (size_t)(row0 + ty * 8 + r) * CC + col0 + tx * 8;
#pragma unroll
        for (int c = 0; c < 8; c++) orow[c] = acc[r][c] + bias[col0 + tx * 8 + c];
    }
}

// ---------------- launch ----------------
extern "C" void kernel_launch(void* const* d_in, const int* in_sizes, int n_in,
                              void* d_out, int out_size) {
    const float* qkv         = (const float*)d_in[0];  // [4,16384,768]
    const float* sim         = (const float*)d_in[1];  // [4,16384,64]
    const float* proj_w      = (const float*)d_in[2];  // [256,256]
    const float* proj_b      = (const float*)d_in[3];  // [256]
    const float* logit_scale = (const float*)d_in[4];  // [1,1]
    float* out = (float*)d_out;

    // 1) category argmax
    k_argmax<<<(BB * NN + 255) / 256, 256>>>(sim);

    // 2) stable counting sort by category
    k_hist<<<dim3(NCH, BB), CHSZ>>>();
    k_scan<<<BB, 256>>>();
    k_scatter<<<2, 256>>>();

    // 3) grouped attention (gather + inverse-scatter fused)
    const int SMEM_ATT = (2 * GS * DD + GS * (GS + 1)) * (int)sizeof(float); // 98816 B
    cudaFuncSetAttribute(k_attn, cudaFuncAttributeMaxDynamicSharedMemorySize, SMEM_ATT);
    k_attn<<<dim3(NG, HH, BB), GS, SMEM_ATT>>>(qkv, logit_scale);

    // 4) projection + bias
    k_proj<<<dim3((BB * NN) / PBM, CC / PBN), 256>>>(proj_w, proj_b, out);
}

// round 2
// speedup vs baseline: 1.1980x; 1.1980x over previous
#include <cuda_runtime.h>
#include <cuda_bf16.h>
#include <math.h>
#include <stdint.h>

// Problem constants (fixed by the benchmark shapes)
#define BB   4
#define NN   16384
#define CC   256
#define C3   768
#define TT   64        // categories
#define HH   8         // heads
#define DD   32        // head dim
#define GS   128       // group size
#define NG   128       // groups per batch
#define NCH  128       // chunks per batch for counting sort
#define CHSZ 128       // tokens per chunk

// -------- scratch (device globals; no runtime allocation allowed) --------
__device__ int   g_tkid[BB * NN];
__device__ int   g_sortidx[BB * NN];
__device__ int   g_hist[BB * TT * NCH];                      // [b][bin][chunk]
__device__ __nv_bfloat16 g_y_hi[(size_t)BB * NN * CC];       // split fp32 -> hi/lo bf16 planes
__device__ __nv_bfloat16 g_y_lo[(size_t)BB * NN * CC];

// ---------------- PTX helpers (Ampere-style mma on sm_103a legacy HMMA pipe) ---------
__device__ __forceinline__ uint32_t smem_u32(const void* p) {
    return (uint32_t)__cvta_generic_to_shared(p);
}
__device__ __forceinline__ void ldm_x4(uint32_t* r, uint32_t a) {
    asm volatile("ldmatrix.sync.aligned.m8n8.x4.shared.b16 {%0,%1,%2,%3},[%4];"
                 : "=r"(r[0]), "=r"(r[1]), "=r"(r[2]), "=r"(r[3]) : "r"(a));
}
__device__ __forceinline__ void ldm_x2(uint32_t& r0, uint32_t& r1, uint32_t a) {
    asm volatile("ldmatrix.sync.aligned.m8n8.x2.shared.b16 {%0,%1},[%2];"
                 : "=r"(r0), "=r"(r1) : "r"(a));
}
__device__ __forceinline__ void mma_bf16(float* c, const uint32_t* a, const uint32_t* b) {
    asm volatile(
        "mma.sync.aligned.m16n8k16.row.col.f32.bf16.bf16.f32 "
        "{%0,%1,%2,%3},{%4,%5,%6,%7},{%8,%9},{%0,%1,%2,%3};"
        : "+f"(c[0]), "+f"(c[1]), "+f"(c[2]), "+f"(c[3])
        : "r"(a[0]), "r"(a[1]), "r"(a[2]), "r"(a[3]), "r"(b[0]), "r"(b[1]));
}

// ---------------- 1) per-token argmax over 64 categories ----------------
__global__ void k_argmax(const float* __restrict__ sim) {
    int idx = blockIdx.x * blockDim.x + threadIdx.x;
    if (idx >= BB * NN) return;
    const float4* p = (const float4*)(sim + (size_t)idx * TT);
    float best = -3.402823466e38f;
    int bi = 0;
#pragma unroll
    for (int i = 0; i < 16; i++) {
        float4 v = p[i];
        if (v.x > best) { best = v.x; bi = 4 * i + 0; }
        if (v.y > best) { best = v.y; bi = 4 * i + 1; }
        if (v.z > best) { best = v.z; bi = 4 * i + 2; }
        if (v.w > best) { best = v.w; bi = 4 * i + 3; }
    }
    g_tkid[idx] = bi;
}

// ---------------- 2a) per-(batch,chunk) key histogram ----------------
__global__ void k_hist() {
    __shared__ int h[TT];
    int ch = blockIdx.x;
    int b  = blockIdx.y;
    if (threadIdx.x < TT) h[threadIdx.x] = 0;
    __syncthreads();
    int key = g_tkid[b * NN + ch * CHSZ + threadIdx.x];
    atomicAdd(&h[key], 1);
    __syncthreads();
    if (threadIdx.x < TT)
        g_hist[(b * TT + threadIdx.x) * NCH + ch] = h[threadIdx.x];
}

// ---------------- 2b) exclusive scan over (bin-major, chunk-minor) ----------------
__global__ void k_scan() {
    __shared__ int tot[256];
    int b = blockIdx.x;
    int* base = g_hist + b * TT * NCH;
    int t = threadIdx.x;
    int v[32];
    int s = 0;
#pragma unroll
    for (int i = 0; i < 32; i++) { v[i] = base[t * 32 + i]; s += v[i]; }
    tot[t] = s;
    __syncthreads();
    if (t == 0) {
        int acc = 0;
        for (int i = 0; i < 256; i++) { int x = tot[i]; tot[i] = acc; acc += x; }
    }
    __syncthreads();
    int ex = tot[t];
#pragma unroll
    for (int i = 0; i < 32; i++) { int x = v[i]; base[t * 32 + i] = ex; ex += x; }
}

// ---------------- 2c) parallel stable scatter ----------------
// Block per (batch, chunk). Stable rank of token i within its chunk among equal
// keys = #{j < i : key_j == key_i}, computed by a broadcast scan over smem keys.
__global__ void k_scatter_par() {
    __shared__ int keys[CHSZ];
    int b  = blockIdx.x / NCH;
    int ch = blockIdx.x % NCH;
    int t  = threadIdx.x;
    int key = g_tkid[b * NN + ch * CHSZ + t];
    keys[t] = key;
    __syncthreads();
    int rank = 0;
    for (int j = 0; j < CHSZ - 1; j++) {            // broadcast reads
        if (j < t && keys[j] == key) rank++;
    }
    int pos = g_hist[(b * TT + key) * NCH + ch] + rank;
    g_sortidx[b * NN + pos] = ch * CHSZ + t;
}

// ---------------- 3) grouped attention, gather + inverse-scatter fused ----------------
// Block = one (b, g, h). 128 threads = one query row each.
// smem: K[128*32] + V[128*32] + S[128*129] = 98816 B dynamic.
extern __shared__ float sm_att[];
__global__ void __launch_bounds__(128, 2)
k_attn(const float* __restrict__ qkv, const float* __restrict__ logit_scale) {
    float* Ks = sm_att;                 // 128 x 32
    float* Vs = sm_att + GS * DD;       // 128 x 32
    float* Ss = sm_att + 2 * GS * DD;   // 128 x 129 (padded rows, conflict-free)

    int g = blockIdx.x, h = blockIdx.y, b = blockIdx.z;
    int q = threadIdx.x;

    int tok = g_sortidx[b * NN + g * GS + q];
    size_t rowbase = (size_t)(b * NN + tok) * C3 + h * DD;

    float qr[DD];
    const float4* qp = (const float4*)(qkv + rowbase);
    const float4* kp = (const float4*)(qkv + rowbase + CC);
    const float4* vp = (const float4*)(qkv + rowbase + 2 * CC);
#pragma unroll
    for (int i = 0; i < 8; i++) {
        float4 x = qp[i];
        qr[4 * i + 0] = x.x; qr[4 * i + 1] = x.y; qr[4 * i + 2] = x.z; qr[4 * i + 3] = x.w;
        ((float4*)(Ks + q * DD))[i] = kp[i];
        ((float4*)(Vs + q * DD))[i] = vp[i];
    }
    float scale = __expf(fminf(logit_scale[0], 4.605170185988091f)); // log(100)
    __syncthreads();

    float* srow = Ss + q * (GS + 1);
    float m = -3.402823466e38f;
#pragma unroll 2
    for (int j = 0; j < GS; j++) {
        const float* kr = Ks + j * DD;
        float a0 = 0.f, a1 = 0.f, a2 = 0.f, a3 = 0.f;   // break the serial FMA chain
#pragma unroll
        for (int kk = 0; kk < DD; kk += 4) {
            a0 += qr[kk + 0] * kr[kk + 0];
            a1 += qr[kk + 1] * kr[kk + 1];
            a2 += qr[kk + 2] * kr[kk + 2];
            a3 += qr[kk + 3] * kr[kk + 3];
        }
        float acc = ((a0 + a1) + (a2 + a3)) * scale;
        srow[j] = acc;
        m = fmaxf(m, acc);
    }

    float sum = 0.0f;
#pragma unroll 4
    for (int j = 0; j < GS; j++) {
        float e = __expf(srow[j] - m);
        srow[j] = e;
        sum += e;
    }
    float inv = 1.0f / sum;

    float acc[DD];
#pragma unroll
    for (int kk = 0; kk < DD; kk++) acc[kk] = 0.0f;
#pragma unroll 2
    for (int j = 0; j < GS; j++) {
        float w = srow[j];
        const float* vr = Vs + j * DD;
#pragma unroll
        for (int kk = 0; kk < DD; kk++) acc[kk] += w * vr[kk];
    }

    // write at ORIGINAL token position (inverse permutation fused), split hi/lo bf16
    size_t obase = (size_t)(b * NN + tok) * CC + h * DD;
    __nv_bfloat162* oh = (__nv_bfloat162*)(g_y_hi + obase);
    __nv_bfloat162* ol = (__nv_bfloat162*)(g_y_lo + obase);
#pragma unroll
    for (int i = 0; i < 16; i++) {
        float v0 = acc[2 * i + 0] * inv;
        float v1 = acc[2 * i + 1] * inv;
        __nv_bfloat16 h0 = __float2bfloat16(v0);
        __nv_bfloat16 h1 = __float2bfloat16(v1);
        __nv_bfloat16 l0 = __float2bfloat16(v0 - __bfloat162float(h0));
        __nv_bfloat16 l1 = __float2bfloat16(v1 - __bfloat162float(h1));
        oh[i] = __nv_bfloat162(h0, h1);
        ol[i] = __nv_bfloat162(l0, l1);
    }
}

// ---------------- 4) projection via bf16x3 tensor-core GEMM ----------------
// out[M=65536, N=256] = y @ W^T + bias, y split into (hi, lo) bf16 planes.
// Block tile 128x64, 4 warps (2x2), warp tile 64x32. BK=32.
#define P_BM 128
#define P_BN 64
#define P_BK 32
#define P_ST 40   // padded smem stride in bf16 (80 B: 16B-aligned, conflict-free for ldmatrix)

__global__ void __launch_bounds__(128, 2)
k_proj_mma(const float* __restrict__ W, const float* __restrict__ bias,
           float* __restrict__ out) {
    __shared__ __nv_bfloat16 Ah[P_BM * P_ST], Al[P_BM * P_ST];
    __shared__ __nv_bfloat16 Bh[P_BN * P_ST], Bl[P_BN * P_ST];

    int tid  = threadIdx.x;
    int lane = tid & 31;
    int warp = tid >> 5;
    int row0 = blockIdx.x * P_BM;
    int col0 = blockIdx.y * P_BN;
    int m_off = (warp & 1) * 64;
    int n_off = (warp >> 1) * 32;

    float c[4][4][4];
#pragma unroll
    for (int mf = 0; mf < 4; mf++)
#pragma unroll
        for (int nf = 0; nf < 4; nf++)
#pragma unroll
            for (int r = 0; r < 4; r++) c[mf][nf][r] = 0.0f;

    for (int k0 = 0; k0 < CC; k0 += P_BK) {
        // A tiles: thread t owns row t; 4 x 16B per plane
        {
            const uint4* sh = (const uint4*)(g_y_hi + (size_t)(row0 + tid) * CC + k0);
            const uint4* sl = (const uint4*)(g_y_lo + (size_t)(row0 + tid) * CC + k0);
            uint4* dh = (uint4*)(Ah + tid * P_ST);
            uint4* dl = (uint4*)(Al + tid * P_ST);
#pragma unroll
            for (int i = 0; i < 4; i++) { dh[i] = sh[i]; dl[i] = sl[i]; }
        }
        // B tiles: W fp32 -> split to bf16 hi/lo in smem. thread t: row t/2, half (t&1)
        {
            int nl = tid >> 1;
            int kh = (tid & 1) * 16;
            const float4* ws = (const float4*)(W + (size_t)(col0 + nl) * CC + k0 + kh);
            __nv_bfloat16* bh = Bh + nl * P_ST + kh;
            __nv_bfloat16* bl = Bl + nl * P_ST + kh;
#pragma unroll
            for (int qd = 0; qd < 4; qd++) {
                float4 w = ws[qd];
                float vv[4] = {w.x, w.y, w.z, w.w};
#pragma unroll
                for (int j = 0; j < 4; j++) {
                    __nv_bfloat16 hi = __float2bfloat16(vv[j]);
                    bh[qd * 4 + j] = hi;
                    bl[qd * 4 + j] = __float2bfloat16(vv[j] - __bfloat162float(hi));
                }
            }
        }
        __syncthreads();

#pragma unroll
        for (int kk = 0; kk < P_BK; kk += 16) {
            uint32_t bh[4][2], bl[4][2];
            int l16 = lane & 15;
#pragma unroll
            for (int nf = 0; nf < 4; nf++) {
                const __nv_bfloat16* ph =
                    Bh + (n_off + nf * 8 + (l16 & 7)) * P_ST + kk + (l16 >> 3) * 8;
                const __nv_bfloat16* pl =
                    Bl + (n_off + nf * 8 + (l16 & 7)) * P_ST + kk + (l16 >> 3) * 8;
                ldm_x2(bh[nf][0], bh[nf][1], smem_u32(ph));
                ldm_x2(bl[nf][0], bl[nf][1], smem_u32(pl));
            }
#pragma unroll
            for (int mf = 0; mf < 4; mf++) {
                uint32_t ah[4], al[4];
                const __nv_bfloat16* pah =
                    Ah + (m_off + mf * 16 + l16) * P_ST + kk + (lane >> 4) * 8;
                const __nv_bfloat16* pal =
                    Al + (m_off + mf * 16 + l16) * P_ST + kk + (lane >> 4) * 8;
                ldm_x4(ah, smem_u32(pah));
                ldm_x4(al, smem_u32(pal));
#pragma unroll
                for (int nf = 0; nf < 4; nf++) {
                    mma_bf16(c[mf][nf], ah, bh[nf]);   // hi*hi
                    mma_bf16(c[mf][nf], ah, bl[nf]);   // hi*lo
                    mma_bf16(c[mf][nf], al, bh[nf]);   // lo*hi
                }
            }
        }
        __syncthreads();
    }

    // epilogue: D + bias
#pragma unroll
    for (int mf = 0; mf < 4; mf++) {
#pragma unroll
        for (int nf = 0; nf < 4; nf++) {
            int rg = row0 + m_off + mf * 16 + (lane >> 2);
            int cg = col0 + n_off + nf * 8 + (lane & 3) * 2;
            float b0 = bias[cg], b1 = bias[cg + 1];
            float2* o0 = (float2*)(out + (size_t)rg * CC + cg);
            float2* o1 = (float2*)(out + (size_t)(rg + 8) * CC + cg);
            *o0 = make_float2(c[mf][nf][0] + b0, c[mf][nf][1] + b1);
            *o1 = make_float2(c[mf][nf][2] + b0, c[mf][nf][3] + b1);
        }
    }
}

// ---------------- launch ----------------
extern "C" void kernel_launch(void* const* d_in, const int* in_sizes, int n_in,
                              void* d_out, int out_size) {
    const float* qkv         = (const float*)d_in[0];  // [4,16384,768]
    const float* sim         = (const float*)d_in[1];  // [4,16384,64]
    const float* proj_w      = (const float*)d_in[2];  // [256,256]
    const float* proj_b      = (const float*)d_in[3];  // [256]
    const float* logit_scale = (const float*)d_in[4];  // [1,1]
    float* out = (float*)d_out;

    // 1) category argmax
    k_argmax<<<(BB * NN + 255) / 256, 256>>>(sim);

    // 2) stable counting sort by category
    k_hist<<<dim3(NCH, BB), CHSZ>>>();
    k_scan<<<BB, 256>>>();
    k_scatter_par<<<BB * NCH, CHSZ>>>();

    // 3) grouped attention (gather + inverse-scatter fused, hi/lo split output)
    const int SMEM_ATT = (2 * GS * DD + GS * (GS + 1)) * (int)sizeof(float); // 98816 B
    cudaFuncSetAttribute(k_attn, cudaFuncAttributeMaxDynamicSharedMemorySize, SMEM_ATT);
    k_attn<<<dim3(NG, HH, BB), GS, SMEM_ATT>>>(qkv, logit_scale);

    // 4) projection + bias on tensor cores (bf16x3)
    k_proj_mma<<<dim3((BB * NN) / P_BM, CC / P_BN), 128>>>(proj_w, proj_b, out);
}

// round 3
// speedup vs baseline: 2.6667x; 2.2260x over previous
#include <cuda_runtime.h>
#include <cuda_bf16.h>
#include <math.h>
#include <stdint.h>

// Problem constants (fixed by the benchmark shapes)
#define BB   4
#define NN   16384
#define CC   256
#define C3   768
#define TT   64        // categories
#define HH   8         // heads
#define DD   32        // head dim
#define GS   128       // group size
#define NG   128       // groups per batch
#define NCH  128       // chunks per batch for counting sort
#define CHSZ 128       // tokens per chunk

// -------- scratch (device globals; no runtime allocation allowed) --------
__device__ int   g_tkid[BB * NN];
__device__ int   g_sortidx[BB * NN];
__device__ int   g_hist[BB * TT * NCH];                      // [b][bin][chunk]
__device__ __nv_bfloat16 g_y_hi[(size_t)BB * NN * CC];       // attention out, hi/lo bf16 planes
__device__ __nv_bfloat16 g_y_lo[(size_t)BB * NN * CC];

// ---------------- PTX helpers ----------------
__device__ __forceinline__ uint32_t smem_u32(const void* p) {
    return (uint32_t)__cvta_generic_to_shared(p);
}
__device__ __forceinline__ void ldm_x4(uint32_t* r, uint32_t a) {
    asm volatile("ldmatrix.sync.aligned.m8n8.x4.shared.b16 {%0,%1,%2,%3},[%4];"
                 : "=r"(r[0]), "=r"(r[1]), "=r"(r[2]), "=r"(r[3]) : "r"(a));
}
__device__ __forceinline__ void ldm_x4_t(uint32_t* r, uint32_t a) {
    asm volatile("ldmatrix.sync.aligned.m8n8.x4.trans.shared.b16 {%0,%1,%2,%3},[%4];"
                 : "=r"(r[0]), "=r"(r[1]), "=r"(r[2]), "=r"(r[3]) : "r"(a));
}
__device__ __forceinline__ void ldm_x2(uint32_t& r0, uint32_t& r1, uint32_t a) {
    asm volatile("ldmatrix.sync.aligned.m8n8.x2.shared.b16 {%0,%1},[%2];"
                 : "=r"(r0), "=r"(r1) : "r"(a));
}
__device__ __forceinline__ void mma_bf16(float* c, const uint32_t* a, uint32_t b0, uint32_t b1) {
    asm volatile(
        "mma.sync.aligned.m16n8k16.row.col.f32.bf16.bf16.f32 "
        "{%0,%1,%2,%3},{%4,%5,%6,%7},{%8,%9},{%0,%1,%2,%3};"
        : "+f"(c[0]), "+f"(c[1]), "+f"(c[2]), "+f"(c[3])
        : "r"(a[0]), "r"(a[1]), "r"(a[2]), "r"(a[3]), "r"(b0), "r"(b1));
}
__device__ __forceinline__ uint32_t packf2(float x, float y) {
    __nv_bfloat162 t = __floats2bfloat162_rn(x, y);
    return *(uint32_t*)&t;
}

// ---------------- 1) per-token argmax over 64 categories ----------------
__global__ void k_argmax(const float* __restrict__ sim) {
    int idx = blockIdx.x * blockDim.x + threadIdx.x;
    if (idx >= BB * NN) return;
    const float4* p = (const float4*)(sim + (size_t)idx * TT);
    float best = -3.402823466e38f;
    int bi = 0;
#pragma unroll
    for (int i = 0; i < 16; i++) {
        float4 v = p[i];
        if (v.x > best) { best = v.x; bi = 4 * i + 0; }
        if (v.y > best) { best = v.y; bi = 4 * i + 1; }
        if (v.z > best) { best = v.z; bi = 4 * i + 2; }
        if (v.w > best) { best = v.w; bi = 4 * i + 3; }
    }
    g_tkid[idx] = bi;
}

// ---------------- 2a) per-(batch,chunk) key histogram ----------------
__global__ void k_hist() {
    __shared__ int h[TT];
    int ch = blockIdx.x;
    int b  = blockIdx.y;
    if (threadIdx.x < TT) h[threadIdx.x] = 0;
    __syncthreads();
    int key = g_tkid[b * NN + ch * CHSZ + threadIdx.x];
    atomicAdd(&h[key], 1);
    __syncthreads();
    if (threadIdx.x < TT)
        g_hist[(b * TT + threadIdx.x) * NCH + ch] = h[threadIdx.x];
}

// ---------------- 2b) exclusive scan ----------------
__global__ void k_scan() {
    __shared__ int tot[256];
    int b = blockIdx.x;
    int* base = g_hist + b * TT * NCH;
    int t = threadIdx.x;
    int v[32];
    int s = 0;
#pragma unroll
    for (int i = 0; i < 32; i++) { v[i] = base[t * 32 + i]; s += v[i]; }
    tot[t] = s;
    __syncthreads();
    if (t == 0) {
        int acc = 0;
        for (int i = 0; i < 256; i++) { int x = tot[i]; tot[i] = acc; acc += x; }
    }
    __syncthreads();
    int ex = tot[t];
#pragma unroll
    for (int i = 0; i < 32; i++) { int x = v[i]; base[t * 32 + i] = ex; ex += x; }
}

// ---------------- 2c) parallel stable scatter ----------------
__global__ void k_scatter_par() {
    __shared__ int keys[CHSZ];
    int b  = blockIdx.x / NCH;
    int ch = blockIdx.x % NCH;
    int t  = threadIdx.x;
    int key = g_tkid[b * NN + ch * CHSZ + t];
    keys[t] = key;
    __syncthreads();
    int rank = 0;
    for (int j = 0; j < CHSZ - 1; j++) {
        if (j < t && keys[j] == key) rank++;
    }
    int pos = g_hist[(b * TT + key) * NCH + ch] + rank;
    g_sortidx[b * NN + pos] = ch * CHSZ + t;
}

// ---------------- 3) tensor-core attention (bf16x3), gather+scatter fused ----------------
// Block = one (b, g, h), 256 threads = 8 warps, warp owns 16 query rows.
// smem planes stride 40 bf16 (80 B, 16B-multiple, ldmatrix friendly).
#define AST 40
#define SM_Q_HI 0
#define SM_Q_LO (128 * AST)
#define SM_K_HI (2 * 128 * AST)
#define SM_K_LO (3 * 128 * AST)
#define SM_V_HI (4 * 128 * AST)
#define SM_V_LO (5 * 128 * AST)
#define SM_TOK  (6 * 128 * AST)            // 128 ints after the planes (element offset in bf16 units)
#define SMEM_ATT_BYTES (6 * 128 * AST * 2 + 128 * 4)

extern __shared__ __align__(16) __nv_bfloat16 sm_att[];

__global__ void __launch_bounds__(256)
k_attn_mma(const float* __restrict__ qkv, const float* __restrict__ logit_scale) {
    __nv_bfloat16* Qh = sm_att + SM_Q_HI;
    __nv_bfloat16* Ql = sm_att + SM_Q_LO;
    __nv_bfloat16* Kh = sm_att + SM_K_HI;
    __nv_bfloat16* Kl = sm_att + SM_K_LO;
    __nv_bfloat16* Vh = sm_att + SM_V_HI;
    __nv_bfloat16* Vl = sm_att + SM_V_LO;
    int* toks = (int*)(sm_att + SM_TOK);

    int g = blockIdx.x, h = blockIdx.y, b = blockIdx.z;
    int tid = threadIdx.x, lane = tid & 31, warp = tid >> 5;

    // ---- load & gather: thread t owns row t/2, 16-float half (t&1) of each tensor ----
    {
        int row = tid >> 1, half = tid & 1;
        int tok = g_sortidx[b * NN + g * GS + row];
        if (half == 0) toks[row] = tok;
        size_t base = (size_t)(b * NN + tok) * C3 + h * DD + half * 16;
        int soff = row * AST + half * 16;
#pragma unroll
        for (int tsel = 0; tsel < 3; tsel++) {
            const float4* src = (const float4*)(qkv + base + tsel * CC);
            __nv_bfloat16* dh = (tsel == 0 ? Qh : tsel == 1 ? Kh : Vh) + soff;
            __nv_bfloat16* dl = (tsel == 0 ? Ql : tsel == 1 ? Kl : Vl) + soff;
#pragma unroll
            for (int i = 0; i < 4; i++) {
                float4 x = src[i];
                __nv_bfloat162 h01 = __floats2bfloat162_rn(x.x, x.y);
                __nv_bfloat162 h23 = __floats2bfloat162_rn(x.z, x.w);
                float2 f01 = __bfloat1622float2(h01);
                float2 f23 = __bfloat1622float2(h23);
                __nv_bfloat162 l01 = __floats2bfloat162_rn(x.x - f01.x, x.y - f01.y);
                __nv_bfloat162 l23 = __floats2bfloat162_rn(x.z - f23.x, x.w - f23.y);
                uint2 ph = make_uint2(*(uint32_t*)&h01, *(uint32_t*)&h23);
                uint2 pl = make_uint2(*(uint32_t*)&l01, *(uint32_t*)&l23);
                *(uint2*)(dh + i * 4) = ph;
                *(uint2*)(dl + i * 4) = pl;
            }
        }
    }
    float scale = __expf(fminf(logit_scale[0], 4.605170185988091f)); // exp(min(ls, log 100))
    __syncthreads();

    int m0 = warp * 16;
    int l16 = lane & 15;

    // ---- Q fragments (A, m16 k32: 2 k-steps), hi & lo ----
    uint32_t qh[2][4], ql[2][4];
#pragma unroll
    for (int ks = 0; ks < 2; ks++) {
        ldm_x4(qh[ks], smem_u32(Qh + (m0 + l16) * AST + ks * 16 + (lane >> 4) * 8));
        ldm_x4(ql[ks], smem_u32(Ql + (m0 + l16) * AST + ks * 16 + (lane >> 4) * 8));
    }

    // ---- S = scale * Q K^T (128 cols = 16 n-frags), bf16x3 ----
    float s[16][4];
#pragma unroll
    for (int nf = 0; nf < 16; nf++)
#pragma unroll
        for (int r = 0; r < 4; r++) s[nf][r] = 0.0f;

#pragma unroll
    for (int p2 = 0; p2 < 8; p2++) {           // pairs of n-frags: j0 = p2*16
        int j0 = p2 * 16;
#pragma unroll
        for (int ks = 0; ks < 2; ks++) {
            uint32_t kb[4], kl4[4];
            // x4: r0,r1 = b-frag(j0..7), r2,r3 = b-frag(j8..15)
            int krow = j0 + ((lane >> 4) << 3) + (lane & 7);
            int kcol = ks * 16 + ((lane >> 3) & 1) * 8;
            ldm_x4(kb,  smem_u32(Kh + krow * AST + kcol));
            ldm_x4(kl4, smem_u32(Kl + krow * AST + kcol));
            mma_bf16(s[2 * p2],     qh[ks], kb[0],  kb[1]);
            mma_bf16(s[2 * p2],     qh[ks], kl4[0], kl4[1]);
            mma_bf16(s[2 * p2],     ql[ks], kb[0],  kb[1]);
            mma_bf16(s[2 * p2 + 1], qh[ks], kb[2],  kb[3]);
            mma_bf16(s[2 * p2 + 1], qh[ks], kl4[2], kl4[3]);
            mma_bf16(s[2 * p2 + 1], ql[ks], kb[2],  kb[3]);
        }
    }

    // ---- softmax over rows (row r = lane>>2 [elems 0,1], r+8 [elems 2,3]) ----
    float m01 = -3.402823466e38f, m23 = -3.402823466e38f;
#pragma unroll
    for (int nf = 0; nf < 16; nf++) {
#pragma unroll
        for (int r = 0; r < 4; r++) s[nf][r] *= scale;
        m01 = fmaxf(m01, fmaxf(s[nf][0], s[nf][1]));
        m23 = fmaxf(m23, fmaxf(s[nf][2], s[nf][3]));
    }
    m01 = fmaxf(m01, __shfl_xor_sync(0xffffffffu, m01, 1));
    m01 = fmaxf(m01, __shfl_xor_sync(0xffffffffu, m01, 2));
    m23 = fmaxf(m23, __shfl_xor_sync(0xffffffffu, m23, 1));
    m23 = fmaxf(m23, __shfl_xor_sync(0xffffffffu, m23, 2));

    float sum01 = 0.0f, sum23 = 0.0f;
#pragma unroll
    for (int nf = 0; nf < 16; nf++) {
        float e0 = __expf(s[nf][0] - m01);
        float e1 = __expf(s[nf][1] - m01);
        float e2 = __expf(s[nf][2] - m23);
        float e3 = __expf(s[nf][3] - m23);
        s[nf][0] = e0; s[nf][1] = e1; s[nf][2] = e2; s[nf][3] = e3;
        sum01 += e0 + e1;
        sum23 += e2 + e3;
    }
    sum01 += __shfl_xor_sync(0xffffffffu, sum01, 1);
    sum01 += __shfl_xor_sync(0xffffffffu, sum01, 2);
    sum23 += __shfl_xor_sync(0xffffffffu, sum23, 1);
    sum23 += __shfl_xor_sync(0xffffffffu, sum23, 2);

    // ---- O = P V (n = 32 = 4 n-frags), P split to bf16 hi/lo from S frags ----
    float o[4][4];
#pragma unroll
    for (int nf = 0; nf < 4; nf++)
#pragma unroll
        for (int r = 0; r < 4; r++) o[nf][r] = 0.0f;

#pragma unroll
    for (int kj = 0; kj < 8; kj++) {           // k-step over j = kj*16
        int f0 = 2 * kj, f1 = 2 * kj + 1;
        uint32_t ph[4], pl[4];
        // hi planes
        __nv_bfloat162 h0 = __floats2bfloat162_rn(s[f0][0], s[f0][1]);
        __nv_bfloat162 h1 = __floats2bfloat162_rn(s[f0][2], s[f0][3]);
        __nv_bfloat162 h2 = __floats2bfloat162_rn(s[f1][0], s[f1][1]);
        __nv_bfloat162 h3 = __floats2bfloat162_rn(s[f1][2], s[f1][3]);
        ph[0] = *(uint32_t*)&h0; ph[1] = *(uint32_t*)&h1;
        ph[2] = *(uint32_t*)&h2; ph[3] = *(uint32_t*)&h3;
        // lo residuals
        float2 g0 = __bfloat1622float2(h0), g1 = __bfloat1622float2(h1);
        float2 g2 = __bfloat1622float2(h2), g3 = __bfloat1622float2(h3);
        pl[0] = packf2(s[f0][0] - g0.x, s[f0][1] - g0.y);
        pl[1] = packf2(s[f0][2] - g1.x, s[f0][3] - g1.y);
        pl[2] = packf2(s[f1][0] - g2.x, s[f1][1] - g2.y);
        pl[3] = packf2(s[f1][2] - g3.x, s[f1][3] - g3.y);

        int vrow = kj * 16 + l16;
#pragma unroll
        for (int dh2 = 0; dh2 < 2; dh2++) {    // d halves: 0-15, 16-31
            uint32_t vh[4], vl[4];
            uint32_t va = smem_u32(Vh + vrow * AST + dh2 * 16 + ((lane >> 4) << 3));
            uint32_t vb = smem_u32(Vl + vrow * AST + dh2 * 16 + ((lane >> 4) << 3));
            ldm_x4_t(vh, va);
            ldm_x4_t(vl, vb);
            mma_bf16(o[2 * dh2],     ph, vh[0], vh[1]);
            mma_bf16(o[2 * dh2],     ph, vl[0], vl[1]);
            mma_bf16(o[2 * dh2],     pl, vh[0], vh[1]);
            mma_bf16(o[2 * dh2 + 1], ph, vh[2], vh[3]);
            mma_bf16(o[2 * dh2 + 1], ph, vl[2], vl[3]);
            mma_bf16(o[2 * dh2 + 1], pl, vh[2], vh[3]);
        }
    }

    // ---- epilogue: normalize, split hi/lo, scatter to ORIGINAL token rows ----
    float inv0 = 1.0f / sum01, inv1 = 1.0f / sum23;
    int r0 = m0 + (lane >> 2);
    int tok0 = toks[r0], tok1 = toks[r0 + 8];
    size_t ob0 = (size_t)(b * NN + tok0) * CC + h * DD + (lane & 3) * 2;
    size_t ob1 = (size_t)(b * NN + tok1) * CC + h * DD + (lane & 3) * 2;
#pragma unroll
    for (int nf = 0; nf < 4; nf++) {
        float v0 = o[nf][0] * inv0, v1 = o[nf][1] * inv0;
        float v2 = o[nf][2] * inv1, v3 = o[nf][3] * inv1;
        __nv_bfloat162 a01 = __floats2bfloat162_rn(v0, v1);
        __nv_bfloat162 a23 = __floats2bfloat162_rn(v2, v3);
        float2 fa = __bfloat1622float2(a01), fb = __bfloat1622float2(a23);
        __nv_bfloat162 b01 = __floats2bfloat162_rn(v0 - fa.x, v1 - fa.y);
        __nv_bfloat162 b23 = __floats2bfloat162_rn(v2 - fb.x, v3 - fb.y);
        *(__nv_bfloat162*)(g_y_hi + ob0 + nf * 8) = a01;
        *(__nv_bfloat162*)(g_y_lo + ob0 + nf * 8) = b01;
        *(__nv_bfloat162*)(g_y_hi + ob1 + nf * 8) = a23;
        *(__nv_bfloat162*)(g_y_lo + ob1 + nf * 8) = b23;
    }
}

// ---------------- 4) projection via bf16x3 tensor-core GEMM ----------------
#define P_BM 128
#define P_BN 64
#define P_BK 32
#define P_ST 40

__global__ void __launch_bounds__(128, 2)
k_proj_mma(const float* __restrict__ W, const float* __restrict__ bias,
           float* __restrict__ out) {
    __shared__ __nv_bfloat16 Ah[P_BM * P_ST], Al[P_BM * P_ST];
    __shared__ __nv_bfloat16 Bh[P_BN * P_ST], Bl[P_BN * P_ST];

    int tid  = threadIdx.x;
    int lane = tid & 31;
    int warp = tid >> 5;
    int row0 = blockIdx.x * P_BM;
    int col0 = blockIdx.y * P_BN;
    int m_off = (warp & 1) * 64;
    int n_off = (warp >> 1) * 32;

    float c[4][4][4];
#pragma unroll
    for (int mf = 0; mf < 4; mf++)
#pragma unroll
        for (int nf = 0; nf < 4; nf++)
#pragma unroll
            for (int r = 0; r < 4; r++) c[mf][nf][r] = 0.0f;

    for (int k0 = 0; k0 < CC; k0 += P_BK) {
        {
            const uint4* sh = (const uint4*)(g_y_hi + (size_t)(row0 + tid) * CC + k0);
            const uint4* sl = (const uint4*)(g_y_lo + (size_t)(row0 + tid) * CC + k0);
            uint4* dh = (uint4*)(Ah + tid * P_ST);
            uint4* dl = (uint4*)(Al + tid * P_ST);
#pragma unroll
            for (int i = 0; i < 4; i++) { dh[i] = sh[i]; dl[i] = sl[i]; }
        }
        {
            int nl = tid >> 1;
            int kh = (tid & 1) * 16;
            const float4* ws = (const float4*)(W + (size_t)(col0 + nl) * CC + k0 + kh);
            __nv_bfloat16* bh = Bh + nl * P_ST + kh;
            __nv_bfloat16* bl = Bl + nl * P_ST + kh;
#pragma unroll
            for (int qd = 0; qd < 4; qd++) {
                float4 w = ws[qd];
                float vv[4] = {w.x, w.y, w.z, w.w};
#pragma unroll
                for (int j = 0; j < 4; j++) {
                    __nv_bfloat16 hi = __float2bfloat16(vv[j]);
                    bh[qd * 4 + j] = hi;
                    bl[qd * 4 + j] = __float2bfloat16(vv[j] - __bfloat162float(hi));
                }
            }
        }
        __syncthreads();

#pragma unroll
        for (int kk = 0; kk < P_BK; kk += 16) {
            uint32_t bh[4][2], bl[4][2];
            int l16 = lane & 15;
#pragma unroll
            for (int nf = 0; nf < 4; nf++) {
                const __nv_bfloat16* ph =
                    Bh + (n_off + nf * 8 + (l16 & 7)) * P_ST + kk + (l16 >> 3) * 8;
                const __nv_bfloat16* pl =
                    Bl + (n_off + nf * 8 + (l16 & 7)) * P_ST + kk + (l16 >> 3) * 8;
                ldm_x2(bh[nf][0], bh[nf][1], smem_u32(ph));
                ldm_x2(bl[nf][0], bl[nf][1], smem_u32(pl));
            }
#pragma unroll
            for (int mf = 0; mf < 4; mf++) {
                uint32_t ah[4], al[4];
                const __nv_bfloat16* pah =
                    Ah + (m_off + mf * 16 + l16) * P_ST + kk + (lane >> 4) * 8;
                const __nv_bfloat16* pal =
                    Al + (m_off + mf * 16 + l16) * P_ST + kk + (lane >> 4) * 8;
                ldm_x4(ah, smem_u32(pah));
                ldm_x4(al, smem_u32(pal));
#pragma unroll
                for (int nf = 0; nf < 4; nf++) {
                    mma_bf16(c[mf][nf], ah, bh[nf][0], bh[nf][1]);
                    mma_bf16(c[mf][nf], ah, bl[nf][0], bl[nf][1]);
                    mma_bf16(c[mf][nf], al, bh[nf][0], bh[nf][1]);
                }
            }
        }
        __syncthreads();
    }

#pragma unroll
    for (int mf = 0; mf < 4; mf++) {
#pragma unroll
        for (int nf = 0; nf < 4; nf++) {
            int rg = row0 + m_off + mf * 16 + (lane >> 2);
            int cg = col0 + n_off + nf * 8 + (lane & 3) * 2;
            float b0 = bias[cg], b1 = bias[cg + 1];
            float2* o0 = (float2*)(out + (size_t)rg * CC + cg);
            float2* o1 = (float2*)(out + (size_t)(rg + 8) * CC + cg);
            *o0 = make_float2(c[mf][nf][0] + b0, c[mf][nf][1] + b1);
            *o1 = make_float2(c[mf][nf][2] + b0, c[mf][nf][3] + b1);
        }
    }
}

// ---------------- launch ----------------
extern "C" void kernel_launch(void* const* d_in, const int* in_sizes, int n_in,
                              void* d_out, int out_size) {
    const float* qkv         = (const float*)d_in[0];  // [4,16384,768]
    const float* sim         = (const float*)d_in[1];  // [4,16384,64]
    const float* proj_w      = (const float*)d_in[2];  // [256,256]
    const float* proj_b      = (const float*)d_in[3];  // [256]
    const float* logit_scale = (const float*)d_in[4];  // [1,1]
    float* out = (float*)d_out;

    // 1) category argmax
    k_argmax<<<(BB * NN + 255) / 256, 256>>>(sim);

    // 2) stable counting sort by category
    k_hist<<<dim3(NCH, BB), CHSZ>>>();
    k_scan<<<BB, 256>>>();
    k_scatter_par<<<BB * NCH, CHSZ>>>();

    // 3) tensor-core grouped attention (gather + inverse-scatter fused)
    cudaFuncSetAttribute(k_attn_mma, cudaFuncAttributeMaxDynamicSharedMemorySize, SMEM_ATT_BYTES);
    k_attn_mma<<<dim3(NG, HH, BB), 256, SMEM_ATT_BYTES>>>(qkv, logit_scale);

    // 4) projection + bias on tensor cores (bf16x3)
    k_proj_mma<<<dim3((BB * NN) / P_BM, CC / P_BN), 128>>>(proj_w, proj_b, out);
}

// round 4
// speedup vs baseline: 3.5060x; 1.3148x over previous
#include <cuda_runtime.h>
#include <cuda_bf16.h>
#include <math.h>
#include <stdint.h>

// Problem constants (fixed by the benchmark shapes)
#define BB   4
#define NN   16384
#define CC   256
#define C3   768
#define TT   64        // categories
#define HH   8         // heads
#define DD   32        // head dim
#define GS   128       // group size
#define NG   128       // groups per batch
#define NCH  128       // chunks per batch for counting sort
#define CHSZ 128       // tokens per chunk

// -------- scratch (device globals; no runtime allocation allowed) --------
__device__ int   g_tkid[BB * NN];
__device__ int   g_sortidx[BB * NN];
__device__ int   g_hist[BB * TT * NCH];                      // [b][bin][chunk]
__device__ __nv_bfloat16 g_y_hi[(size_t)BB * NN * CC];       // attention out, hi/lo bf16 planes
__device__ __nv_bfloat16 g_y_lo[(size_t)BB * NN * CC];
__device__ __nv_bfloat16 g_w_hi[CC * CC];                    // W split planes
__device__ __nv_bfloat16 g_w_lo[CC * CC];

// ---------------- PTX helpers ----------------
__device__ __forceinline__ uint32_t smem_u32(const void* p) {
    return (uint32_t)__cvta_generic_to_shared(p);
}
__device__ __forceinline__ void ldm_x4(uint32_t* r, uint32_t a) {
    asm volatile("ldmatrix.sync.aligned.m8n8.x4.shared.b16 {%0,%1,%2,%3},[%4];"
                 : "=r"(r[0]), "=r"(r[1]), "=r"(r[2]), "=r"(r[3]) : "r"(a));
}
__device__ __forceinline__ void ldm_x4_t(uint32_t* r, uint32_t a) {
    asm volatile("ldmatrix.sync.aligned.m8n8.x4.trans.shared.b16 {%0,%1,%2,%3},[%4];"
                 : "=r"(r[0]), "=r"(r[1]), "=r"(r[2]), "=r"(r[3]) : "r"(a));
}
__device__ __forceinline__ void mma_bf16(float* c, const uint32_t* a, uint32_t b0, uint32_t b1) {
    asm volatile(
        "mma.sync.aligned.m16n8k16.row.col.f32.bf16.bf16.f32 "
        "{%0,%1,%2,%3},{%4,%5,%6,%7},{%8,%9},{%0,%1,%2,%3};"
        : "+f"(c[0]), "+f"(c[1]), "+f"(c[2]), "+f"(c[3])
        : "r"(a[0]), "r"(a[1]), "r"(a[2]), "r"(a[3]), "r"(b0), "r"(b1));
}
__device__ __forceinline__ uint32_t packf2(float x, float y) {
    __nv_bfloat162 t = __floats2bfloat162_rn(x, y);
    return *(uint32_t*)&t;
}
__device__ __forceinline__ void cp16(void* smem_dst, const void* gsrc) {
    asm volatile("cp.async.cg.shared.global [%0], [%1], 16;"
                 :: "r"(smem_u32(smem_dst)), "l"(gsrc));
}
#define CP_COMMIT()  asm volatile("cp.async.commit_group;")
#define CP_WAIT(N)   asm volatile("cp.async.wait_group %0;" :: "n"(N))

extern __shared__ __align__(16) char dynsm[];

// ---------------- 1+2a) fused argmax + per-chunk histogram ----------------
// One block per (b, chunk), 128 threads = one token each.
__global__ void k_argmax_hist(const float* __restrict__ sim) {
    __shared__ int h[TT];
    int b  = blockIdx.x / NCH;
    int ch = blockIdx.x % NCH;
    int t  = threadIdx.x;
    if (t < TT) h[t] = 0;
    int idx = b * NN + ch * CHSZ + t;
    const float4* p = (const float4*)(sim + (size_t)idx * TT);
    float best = -3.402823466e38f;
    int bi = 0;
#pragma unroll
    for (int i = 0; i < 16; i++) {
        float4 v = p[i];
        if (v.x > best) { best = v.x; bi = 4 * i + 0; }
        if (v.y > best) { best = v.y; bi = 4 * i + 1; }
        if (v.z > best) { best = v.z; bi = 4 * i + 2; }
        if (v.w > best) { best = v.w; bi = 4 * i + 3; }
    }
    g_tkid[idx] = bi;
    __syncthreads();
    atomicAdd(&h[bi], 1);
    __syncthreads();
    if (t < TT)
        g_hist[(b * TT + t) * NCH + ch] = h[t];
}

// ---------------- 2b) exclusive scan ----------------
__global__ void k_scan() {
    __shared__ int tot[256];
    int b = blockIdx.x;
    int* base = g_hist + b * TT * NCH;
    int t = threadIdx.x;
    int v[32];
    int s = 0;
#pragma unroll
    for (int i = 0; i < 32; i++) { v[i] = base[t * 32 + i]; s += v[i]; }
    tot[t] = s;
    __syncthreads();
    if (t == 0) {
        int acc = 0;
        for (int i = 0; i < 256; i++) { int x = tot[i]; tot[i] = acc; acc += x; }
    }
    __syncthreads();
    int ex = tot[t];
#pragma unroll
    for (int i = 0; i < 32; i++) { int x = v[i]; base[t * 32 + i] = ex; ex += x; }
}

// ---------------- 2c) parallel stable scatter ----------------
__global__ void k_scatter_par() {
    __shared__ int keys[CHSZ];
    int b  = blockIdx.x / NCH;
    int ch = blockIdx.x % NCH;
    int t  = threadIdx.x;
    int key = g_tkid[b * NN + ch * CHSZ + t];
    keys[t] = key;
    __syncthreads();
    int rank = 0;
    for (int j = 0; j < CHSZ - 1; j++) {
        if (j < t && keys[j] == key) rank++;
    }
    int pos = g_hist[(b * TT + key) * NCH + ch] + rank;
    g_sortidx[b * NN + pos] = ch * CHSZ + t;
}

// ---------------- W split (fp32 -> bf16 hi/lo planes) ----------------
__global__ void k_wsplit(const float* __restrict__ W) {
    int i = blockIdx.x * blockDim.x + threadIdx.x;
    if (i >= CC * CC) return;
    float v = W[i];
    __nv_bfloat16 hi = __float2bfloat16(v);
    g_w_hi[i] = hi;
    g_w_lo[i] = __float2bfloat16(v - __bfloat162float(hi));
}

// ---------------- 3) tensor-core attention (bf16x3), gather+scatter fused ----------------
// Block = one (b, g, h), 256 threads = 8 warps, warp owns 16 query rows.
#define AST 40
#define SM_Q_HI 0
#define SM_Q_LO (128 * AST)
#define SM_K_HI (2 * 128 * AST)
#define SM_K_LO (3 * 128 * AST)
#define SM_V_HI (4 * 128 * AST)
#define SM_V_LO (5 * 128 * AST)
#define SM_TOK  (6 * 128 * AST)
#define SMEM_ATT_BYTES (6 * 128 * AST * 2 + 128 * 4)

__global__ void __launch_bounds__(256)
k_attn_mma(const float* __restrict__ qkv, const float* __restrict__ logit_scale) {
    __nv_bfloat16* sm = (__nv_bfloat16*)dynsm;
    __nv_bfloat16* Qh = sm + SM_Q_HI;
    __nv_bfloat16* Ql = sm + SM_Q_LO;
    __nv_bfloat16* Kh = sm + SM_K_HI;
    __nv_bfloat16* Kl = sm + SM_K_LO;
    __nv_bfloat16* Vh = sm + SM_V_HI;
    __nv_bfloat16* Vl = sm + SM_V_LO;
    int* toks = (int*)(sm + SM_TOK);

    int g = blockIdx.x, h = blockIdx.y, b = blockIdx.z;
    int tid = threadIdx.x, lane = tid & 31, warp = tid >> 5;

    // ---- load & gather: thread t owns row t/2, 16-float half (t&1) of each tensor ----
    {
        int row = tid >> 1, half = tid & 1;
        int tok = g_sortidx[b * NN + g * GS + row];
        if (half == 0) toks[row] = tok;
        size_t base = (size_t)(b * NN + tok) * C3 + h * DD + half * 16;
        int soff = row * AST + half * 16;
#pragma unroll
        for (int tsel = 0; tsel < 3; tsel++) {
            const float4* src = (const float4*)(qkv + base + tsel * CC);
            __nv_bfloat16* dh = (tsel == 0 ? Qh : tsel == 1 ? Kh : Vh) + soff;
            __nv_bfloat16* dl = (tsel == 0 ? Ql : tsel == 1 ? Kl : Vl) + soff;
#pragma unroll
            for (int i = 0; i < 4; i++) {
                float4 x = src[i];
                __nv_bfloat162 h01 = __floats2bfloat162_rn(x.x, x.y);
                __nv_bfloat162 h23 = __floats2bfloat162_rn(x.z, x.w);
                float2 f01 = __bfloat1622float2(h01);
                float2 f23 = __bfloat1622float2(h23);
                __nv_bfloat162 l01 = __floats2bfloat162_rn(x.x - f01.x, x.y - f01.y);
                __nv_bfloat162 l23 = __floats2bfloat162_rn(x.z - f23.x, x.w - f23.y);
                uint2 ph = make_uint2(*(uint32_t*)&h01, *(uint32_t*)&h23);
                uint2 pl = make_uint2(*(uint32_t*)&l01, *(uint32_t*)&l23);
                *(uint2*)(dh + i * 4) = ph;
                *(uint2*)(dl + i * 4) = pl;
            }
        }
    }
    float scale = __expf(fminf(logit_scale[0], 4.605170185988091f));
    __syncthreads();

    int m0 = warp * 16;
    int l16 = lane & 15;

    uint32_t qh[2][4], ql[2][4];
#pragma unroll
    for (int ks = 0; ks < 2; ks++) {
        ldm_x4(qh[ks], smem_u32(Qh + (m0 + l16) * AST + ks * 16 + (lane >> 4) * 8));
        ldm_x4(ql[ks], smem_u32(Ql + (m0 + l16) * AST + ks * 16 + (lane >> 4) * 8));
    }

    float s[16][4];
#pragma unroll
    for (int nf = 0; nf < 16; nf++)
#pragma unroll
        for (int r = 0; r < 4; r++) s[nf][r] = 0.0f;

#pragma unroll
    for (int p2 = 0; p2 < 8; p2++) {
        int j0 = p2 * 16;
#pragma unroll
        for (int ks = 0; ks < 2; ks++) {
            uint32_t kb[4], kl4[4];
            int krow = j0 + ((lane >> 4) << 3) + (lane & 7);
            int kcol = ks * 16 + ((lane >> 3) & 1) * 8;
            ldm_x4(kb,  smem_u32(Kh + krow * AST + kcol));
            ldm_x4(kl4, smem_u32(Kl + krow * AST + kcol));
            mma_bf16(s[2 * p2],     qh[ks], kb[0],  kb[1]);
            mma_bf16(s[2 * p2],     qh[ks], kl4[0], kl4[1]);
            mma_bf16(s[2 * p2],     ql[ks], kb[0],  kb[1]);
            mma_bf16(s[2 * p2 + 1], qh[ks], kb[2],  kb[3]);
            mma_bf16(s[2 * p2 + 1], qh[ks], kl4[2], kl4[3]);
            mma_bf16(s[2 * p2 + 1], ql[ks], kb[2],  kb[3]);
        }
    }

    float m01 = -3.402823466e38f, m23 = -3.402823466e38f;
#pragma unroll
    for (int nf = 0; nf < 16; nf++) {
#pragma unroll
        for (int r = 0; r < 4; r++) s[nf][r] *= scale;
        m01 = fmaxf(m01, fmaxf(s[nf][0], s[nf][1]));
        m23 = fmaxf(m23, fmaxf(s[nf][2], s[nf][3]));
    }
    m01 = fmaxf(m01, __shfl_xor_sync(0xffffffffu, m01, 1));
    m01 = fmaxf(m01, __shfl_xor_sync(0xffffffffu, m01, 2));
    m23 = fmaxf(m23, __shfl_xor_sync(0xffffffffu, m23, 1));
    m23 = fmaxf(m23, __shfl_xor_sync(0xffffffffu, m23, 2));

    float sum01 = 0.0f, sum23 = 0.0f;
#pragma unroll
    for (int nf = 0; nf < 16; nf++) {
        float e0 = __expf(s[nf][0] - m01);
        float e1 = __expf(s[nf][1] - m01);
        float e2 = __expf(s[nf][2] - m23);
        float e3 = __expf(s[nf][3] - m23);
        s[nf][0] = e0; s[nf][1] = e1; s[nf][2] = e2; s[nf][3] = e3;
        sum01 += e0 + e1;
        sum23 += e2 + e3;
    }
    sum01 += __shfl_xor_sync(0xffffffffu, sum01, 1);
    sum01 += __shfl_xor_sync(0xffffffffu, sum01, 2);
    sum23 += __shfl_xor_sync(0xffffffffu, sum23, 1);
    sum23 += __shfl_xor_sync(0xffffffffu, sum23, 2);

    float o[4][4];
#pragma unroll
    for (int nf = 0; nf < 4; nf++)
#pragma unroll
        for (int r = 0; r < 4; r++) o[nf][r] = 0.0f;

#pragma unroll
    for (int kj = 0; kj < 8; kj++) {
        int f0 = 2 * kj, f1 = 2 * kj + 1;
        uint32_t ph[4], pl[4];
        __nv_bfloat162 h0 = __floats2bfloat162_rn(s[f0][0], s[f0][1]);
        __nv_bfloat162 h1 = __floats2bfloat162_rn(s[f0][2], s[f0][3]);
        __nv_bfloat162 h2 = __floats2bfloat162_rn(s[f1][0], s[f1][1]);
        __nv_bfloat162 h3 = __floats2bfloat162_rn(s[f1][2], s[f1][3]);
        ph[0] = *(uint32_t*)&h0; ph[1] = *(uint32_t*)&h1;
        ph[2] = *(uint32_t*)&h2; ph[3] = *(uint32_t*)&h3;
        float2 g0 = __bfloat1622float2(h0), g1 = __bfloat1622float2(h1);
        float2 g2 = __bfloat1622float2(h2), g3 = __bfloat1622float2(h3);
        pl[0] = packf2(s[f0][0] - g0.x, s[f0][1] - g0.y);
        pl[1] = packf2(s[f0][2] - g1.x, s[f0][3] - g1.y);
        pl[2] = packf2(s[f1][0] - g2.x, s[f1][1] - g2.y);
        pl[3] = packf2(s[f1][2] - g3.x, s[f1][3] - g3.y);

        int vrow = kj * 16 + l16;
#pragma unroll
        for (int dh2 = 0; dh2 < 2; dh2++) {
            uint32_t vh[4], vl[4];
            ldm_x4_t(vh, smem_u32(Vh + vrow * AST + dh2 * 16 + ((lane >> 4) << 3)));
            ldm_x4_t(vl, smem_u32(Vl + vrow * AST + dh2 * 16 + ((lane >> 4) << 3)));
            mma_bf16(o[2 * dh2],     ph, vh[0], vh[1]);
            mma_bf16(o[2 * dh2],     ph, vl[0], vl[1]);
            mma_bf16(o[2 * dh2],     pl, vh[0], vh[1]);
            mma_bf16(o[2 * dh2 + 1], ph, vh[2], vh[3]);
            mma_bf16(o[2 * dh2 + 1], ph, vl[2], vl[3]);
            mma_bf16(o[2 * dh2 + 1], pl, vh[2], vh[3]);
        }
    }

    float inv0 = 1.0f / sum01, inv1 = 1.0f / sum23;
    int r0 = m0 + (lane >> 2);
    int tok0 = toks[r0], tok1 = toks[r0 + 8];
    size_t ob0 = (size_t)(b * NN + tok0) * CC + h * DD + (lane & 3) * 2;
    size_t ob1 = (size_t)(b * NN + tok1) * CC + h * DD + (lane & 3) * 2;
#pragma unroll
    for (int nf = 0; nf < 4; nf++) {
        float v0 = o[nf][0] * inv0, v1 = o[nf][1] * inv0;
        float v2 = o[nf][2] * inv1, v3 = o[nf][3] * inv1;
        __nv_bfloat162 a01 = __floats2bfloat162_rn(v0, v1);
        __nv_bfloat162 a23 = __floats2bfloat162_rn(v2, v3);
        float2 fa = __bfloat1622float2(a01), fb = __bfloat1622float2(a23);
        __nv_bfloat162 b01 = __floats2bfloat162_rn(v0 - fa.x, v1 - fa.y);
        __nv_bfloat162 b23 = __floats2bfloat162_rn(v2 - fb.x, v3 - fb.y);
        *(__nv_bfloat162*)(g_y_hi + ob0 + nf * 8) = a01;
        *(__nv_bfloat162*)(g_y_lo + ob0 + nf * 8) = b01;
        *(__nv_bfloat162*)(g_y_hi + ob1 + nf * 8) = a23;
        *(__nv_bfloat162*)(g_y_lo + ob1 + nf * 8) = b23;
    }
}

// ---------------- 4) projection v2: bf16x3 MMA, cp.async double-buffered ----------------
// out[65536,256] = y @ W^T + bias. BM=128, BN=128, BK=32, 256 threads.
// Warp grid 4(m) x 2(n): warp tile 32 x 64.
#define PST  40
#define PPL  (128 * PST)                 // elems per plane
#define PSTG (4 * PPL)                   // elems per stage (Ah, Al, Bh, Bl)
#define SMEM_PROJ_BYTES (2 * PSTG * 2)   // 2 stages x 4 planes x 128*40 bf16

__global__ void __launch_bounds__(256)
k_proj2(const float* __restrict__ bias, float* __restrict__ out) {
    __nv_bfloat16* sm = (__nv_bfloat16*)dynsm;

    int tid  = threadIdx.x;
    int lane = tid & 31;
    int warp = tid >> 5;
    int row0 = blockIdx.x * 128;
    int col0 = blockIdx.y * 128;
    int m_off = (warp & 3) * 32;
    int n_off = (warp >> 2) * 64;
    int l16 = lane & 15;

    // per-thread cp.async assignment: 2 chunks (16B) per plane per stage
    int c0 = tid * 2;
    int rA0 = c0 >> 2, qA0 = (c0 & 3) * 8;        // chunk -> (row, 8-elem col)
    int rA1 = (c0 + 1) >> 2, qA1 = ((c0 + 1) & 3) * 8;

    const __nv_bfloat16* gA_hi = g_y_hi + (size_t)row0 * CC;
    const __nv_bfloat16* gA_lo = g_y_lo + (size_t)row0 * CC;
    const __nv_bfloat16* gB_hi = g_w_hi + (size_t)col0 * CC;
    const __nv_bfloat16* gB_lo = g_w_lo + (size_t)col0 * CC;

    auto load_stage = [&](int st, int k0) {
        __nv_bfloat16* Ah = sm + st * PSTG;
        __nv_bfloat16* Al = Ah + PPL;
        __nv_bfloat16* Bh = Al + PPL;
        __nv_bfloat16* Bl = Bh + PPL;
        cp16(Ah + rA0 * PST + qA0, gA_hi + (size_t)rA0 * CC + k0 + qA0);
        cp16(Ah + rA1 * PST + qA1, gA_hi + (size_t)rA1 * CC + k0 + qA1);
        cp16(Al + rA0 * PST + qA0, gA_lo + (size_t)rA0 * CC + k0 + qA0);
        cp16(Al + rA1 * PST + qA1, gA_lo + (size_t)rA1 * CC + k0 + qA1);
        cp16(Bh + rA0 * PST + qA0, gB_hi + (size_t)rA0 * CC + k0 + qA0);
        cp16(Bh + rA1 * PST + qA1, gB_hi + (size_t)rA1 * CC + k0 + qA1);
        cp16(Bl + rA0 * PST + qA0, gB_lo + (size_t)rA0 * CC + k0 + qA0);
        cp16(Bl + rA1 * PST + qA1, gB_lo + (size_t)rA1 * CC + k0 + qA1);
        CP_COMMIT();
    };

    float c[2][8][4];
#pragma unroll
    for (int mf = 0; mf < 2; mf++)
#pragma unroll
        for (int nf = 0; nf < 8; nf++)
#pragma unroll
            for (int r = 0; r < 4; r++) c[mf][nf][r] = 0.0f;

    load_stage(0, 0);

    for (int kt = 0; kt < 8; kt++) {
        if (kt + 1 < 8) {
            load_stage((kt + 1) & 1, (kt + 1) * 32);
            CP_WAIT(1);
        } else {
            CP_WAIT(0);
        }
        __syncthreads();

        __nv_bfloat16* Ah = sm + (kt & 1) * PSTG;
        __nv_bfloat16* Al = Ah + PPL;
        __nv_bfloat16* Bh = Al + PPL;
        __nv_bfloat16* Bl = Bh + PPL;

#pragma unroll
        for (int kk = 0; kk < 32; kk += 16) {
            // B fragments: 8 n-frags (64 cols) via 4 paired ldm_x4 per plane
            uint32_t bh[8][2], bl[8][2];
#pragma unroll
            for (int np = 0; np < 4; np++) {
                uint32_t t4[4];
                int brow = n_off + np * 16 + ((lane >> 4) << 3) + (lane & 7);
                int bcol = kk + ((lane >> 3) & 1) * 8;
                ldm_x4(t4, smem_u32(Bh + brow * PST + bcol));
                bh[2 * np][0] = t4[0]; bh[2 * np][1] = t4[1];
                bh[2 * np + 1][0] = t4[2]; bh[2 * np + 1][1] = t4[3];
                ldm_x4(t4, smem_u32(Bl + brow * PST + bcol));
                bl[2 * np][0] = t4[0]; bl[2 * np][1] = t4[1];
                bl[2 * np + 1][0] = t4[2]; bl[2 * np + 1][1] = t4[3];
            }
#pragma unroll
            for (int mf = 0; mf < 2; mf++) {
                uint32_t ah[4], al[4];
                int arow = m_off + mf * 16 + l16;
                ldm_x4(ah, smem_u32(Ah + arow * PST + kk + (lane >> 4) * 8));
                ldm_x4(al, smem_u32(Al + arow * PST + kk + (lane >> 4) * 8));
#pragma unroll
                for (int nf = 0; nf < 8; nf++) {
                    mma_bf16(c[mf][nf], ah, bh[nf][0], bh[nf][1]);
                    mma_bf16(c[mf][nf], ah, bl[nf][0], bl[nf][1]);
                    mma_bf16(c[mf][nf], al, bh[nf][0], bh[nf][1]);
                }
            }
        }
        __syncthreads();
    }

    // epilogue: D + bias
#pragma unroll
    for (int mf = 0; mf < 2; mf++) {
#pragma unroll
        for (int nf = 0; nf < 8; nf++) {
            int rg = row0 + m_off + mf * 16 + (lane >> 2);
            int cg = col0 + n_off + nf * 8 + (lane & 3) * 2;
            float b0 = bias[cg], b1 = bias[cg + 1];
            float2* o0 = (float2*)(out + (size_t)rg * CC + cg);
            float2* o1 = (float2*)(out + (size_t)(rg + 8) * CC + cg);
            *o0 = make_float2(c[mf][nf][0] + b0, c[mf][nf][1] + b1);
            *o1 = make_float2(c[mf][nf][2] + b0, c[mf][nf][3] + b1);
        }
    }
}

// ---------------- launch ----------------
extern "C" void kernel_launch(void* const* d_in, const int* in_sizes, int n_in,
                              void* d_out, int out_size) {
    const float* qkv         = (const float*)d_in[0];  // [4,16384,768]
    const float* sim         = (const float*)d_in[1];  // [4,16384,64]
    const float* proj_w      = (const float*)d_in[2];  // [256,256]
    const float* proj_b      = (const float*)d_in[3];  // [256]
    const float* logit_scale = (const float*)d_in[4];  // [1,1]
    float* out = (float*)d_out;

    // 1+2a) fused argmax + histogram
    k_argmax_hist<<<BB * NCH, CHSZ>>>(sim);

    // W split (independent; overlaps conceptually, tiny)
    k_wsplit<<<(CC * CC + 255) / 256, 256>>>(proj_w);

    // 2b/2c) scan + stable scatter
    k_scan<<<BB, 256>>>();
    k_scatter_par<<<BB * NCH, CHSZ>>>();

    // 3) tensor-core grouped attention (gather + inverse-scatter fused)
    cudaFuncSetAttribute(k_attn_mma, cudaFuncAttributeMaxDynamicSharedMemorySize, SMEM_ATT_BYTES);
    k_attn_mma<<<dim3(NG, HH, BB), 256, SMEM_ATT_BYTES>>>(qkv, logit_scale);

    // 4) projection + bias, double-buffered bf16x3 MMA
    cudaFuncSetAttribute(k_proj2, cudaFuncAttributeMaxDynamicSharedMemorySize, SMEM_PROJ_BYTES);
    k_proj2<<<dim3((BB * NN) / 128, CC / 128), 256, SMEM_PROJ_BYTES>>>(proj_b, out);
}

// round 5
// speedup vs baseline: 3.8605x; 1.1011x over previous
#include <cuda_runtime.h>
#include <cuda_bf16.h>
#include <cuda_fp16.h>
#include <math.h>
#include <stdint.h>

// Problem constants (fixed by the benchmark shapes)
#define BB   4
#define NN   16384
#define CC   256
#define C3   768
#define TT   64        // categories
#define HH   8         // heads
#define DD   32        // head dim
#define GS   128       // group size
#define NG   128       // groups per batch
#define NCH  128       // chunks per batch for counting sort
#define CHSZ 128       // tokens per chunk

// -------- scratch (device globals; no runtime allocation allowed) --------
__device__ int   g_tkid[BB * NN];
__device__ int   g_sortidx[BB * NN];
__device__ int   g_hist[BB * TT * NCH];                      // [b][bin][chunk]
__device__ __nv_bfloat16 g_y_hi[(size_t)BB * NN * CC];       // attention out, hi/lo bf16 planes
__device__ __nv_bfloat16 g_y_lo[(size_t)BB * NN * CC];
__device__ __nv_bfloat16 g_w_hi[CC * CC];                    // W split planes
__device__ __nv_bfloat16 g_w_lo[CC * CC];

// ---------------- PTX helpers ----------------
__device__ __forceinline__ uint32_t smem_u32(const void* p) {
    return (uint32_t)__cvta_generic_to_shared(p);
}
__device__ __forceinline__ void ldm_x4(uint32_t* r, uint32_t a) {
    asm volatile("ldmatrix.sync.aligned.m8n8.x4.shared.b16 {%0,%1,%2,%3},[%4];"
                 : "=r"(r[0]), "=r"(r[1]), "=r"(r[2]), "=r"(r[3]) : "r"(a));
}
__device__ __forceinline__ void ldm_x4_t(uint32_t* r, uint32_t a) {
    asm volatile("ldmatrix.sync.aligned.m8n8.x4.trans.shared.b16 {%0,%1,%2,%3},[%4];"
                 : "=r"(r[0]), "=r"(r[1]), "=r"(r[2]), "=r"(r[3]) : "r"(a));
}
__device__ __forceinline__ void mma_bf16(float* c, const uint32_t* a, uint32_t b0, uint32_t b1) {
    asm volatile(
        "mma.sync.aligned.m16n8k16.row.col.f32.bf16.bf16.f32 "
        "{%0,%1,%2,%3},{%4,%5,%6,%7},{%8,%9},{%0,%1,%2,%3};"
        : "+f"(c[0]), "+f"(c[1]), "+f"(c[2]), "+f"(c[3])
        : "r"(a[0]), "r"(a[1]), "r"(a[2]), "r"(a[3]), "r"(b0), "r"(b1));
}
__device__ __forceinline__ void mma_f16(float* c, const uint32_t* a, uint32_t b0, uint32_t b1) {
    asm volatile(
        "mma.sync.aligned.m16n8k16.row.col.f32.f16.f16.f32 "
        "{%0,%1,%2,%3},{%4,%5,%6,%7},{%8,%9},{%0,%1,%2,%3};"
        : "+f"(c[0]), "+f"(c[1]), "+f"(c[2]), "+f"(c[3])
        : "r"(a[0]), "r"(a[1]), "r"(a[2]), "r"(a[3]), "r"(b0), "r"(b1));
}
__device__ __forceinline__ uint32_t packh2(float x, float y) {
    __half2 t = __floats2half2_rn(x, y);
    return *(uint32_t*)&t;
}
__device__ __forceinline__ void cp16(void* smem_dst, const void* gsrc) {
    asm volatile("cp.async.cg.shared.global [%0], [%1], 16;"
                 :: "r"(smem_u32(smem_dst)), "l"(gsrc));
}
#define CP_COMMIT()  asm volatile("cp.async.commit_group;")
#define CP_WAIT(N)   asm volatile("cp.async.wait_group %0;" :: "n"(N))

extern __shared__ __align__(16) char dynsm[];

// ---------------- 1+2a) fused argmax + per-chunk histogram + W split ----------------
// One block per (b, chunk), 128 threads = one token each.
// Grid (512) x block (128) = 65536 threads == CC*CC, so W-split rides along free.
__global__ void k_argmax_hist(const float* __restrict__ sim, const float* __restrict__ W) {
    __shared__ int h[TT];
    int b  = blockIdx.x / NCH;
    int ch = blockIdx.x % NCH;
    int t  = threadIdx.x;

    // W split (one element per thread across the whole grid)
    {
        int wi = blockIdx.x * CHSZ + t;
        float v = W[wi];
        __nv_bfloat16 hi = __float2bfloat16(v);
        g_w_hi[wi] = hi;
        g_w_lo[wi] = __float2bfloat16(v - __bfloat162float(hi));
    }

    if (t < TT) h[t] = 0;
    int idx = b * NN + ch * CHSZ + t;
    const float4* p = (const float4*)(sim + (size_t)idx * TT);
    float best = -3.402823466e38f;
    int bi = 0;
#pragma unroll
    for (int i = 0; i < 16; i++) {
        float4 v = p[i];
        if (v.x > best) { best = v.x; bi = 4 * i + 0; }
        if (v.y > best) { best = v.y; bi = 4 * i + 1; }
        if (v.z > best) { best = v.z; bi = 4 * i + 2; }
        if (v.w > best) { best = v.w; bi = 4 * i + 3; }
    }
    g_tkid[idx] = bi;
    __syncthreads();
    atomicAdd(&h[bi], 1);
    __syncthreads();
    if (t < TT)
        g_hist[(b * TT + t) * NCH + ch] = h[t];
}

// ---------------- 2b) exclusive scan ----------------
__global__ void k_scan() {
    __shared__ int tot[256];
    int b = blockIdx.x;
    int* base = g_hist + b * TT * NCH;
    int t = threadIdx.x;
    int v[32];
    int s = 0;
#pragma unroll
    for (int i = 0; i < 32; i++) { v[i] = base[t * 32 + i]; s += v[i]; }
    tot[t] = s;
    __syncthreads();
    if (t == 0) {
        int acc = 0;
        for (int i = 0; i < 256; i++) { int x = tot[i]; tot[i] = acc; acc += x; }
    }
    __syncthreads();
    int ex = tot[t];
#pragma unroll
    for (int i = 0; i < 32; i++) { int x = v[i]; base[t * 32 + i] = ex; ex += x; }
}

// ---------------- 2c) parallel stable scatter (match/ballot ranks) ----------------
__global__ void k_scatter_par() {
    __shared__ int whist[4][TT];       // per-warp key histogram
    int b  = blockIdx.x / NCH;
    int ch = blockIdx.x % NCH;
    int t  = threadIdx.x;
    int lane = t & 31, w = t >> 5;
    // zero 4*64 ints with 128 threads
    ((int*)whist)[t] = 0;
    ((int*)whist)[t + 128] = 0;
    int key = g_tkid[b * NN + ch * CHSZ + t];
    __syncthreads();
    unsigned mask = __match_any_sync(0xffffffffu, key);
    int wrank = __popc(mask & ((1u << lane) - 1u));
    if (lane == (__ffs(mask) - 1))
        whist[w][key] = __popc(mask);
    __syncthreads();
    int off = 0;
#pragma unroll
    for (int w2 = 0; w2 < 3; w2++)
        if (w2 < w) off += whist[w2][key];
    int pos = g_hist[(b * TT + key) * NCH + ch] + off + wrank;
    g_sortidx[b * NN + pos] = ch * CHSZ + t;
}

// ---------------- 3) tensor-core attention, gather+scatter fused ----------------
// Block = one (b, g, h), 256 threads = 8 warps, warp owns 16 query rows.
// QK^T: bf16x3 (3-term). PV: fp16 single-term (P in [0,1], V well in fp16 range).
#define AST 40
#define SM_Q_HI 0
#define SM_Q_LO (128 * AST)
#define SM_K_HI (2 * 128 * AST)
#define SM_K_LO (3 * 128 * AST)
#define SM_VF   (4 * 128 * AST)
#define SM_TOK  (5 * 128 * AST)
#define SMEM_ATT_BYTES (5 * 128 * AST * 2 + 128 * 4)

__global__ void __launch_bounds__(256)
k_attn_mma(const float* __restrict__ qkv, const float* __restrict__ logit_scale) {
    __nv_bfloat16* sm = (__nv_bfloat16*)dynsm;
    __nv_bfloat16* Qh = sm + SM_Q_HI;
    __nv_bfloat16* Ql = sm + SM_Q_LO;
    __nv_bfloat16* Kh = sm + SM_K_HI;
    __nv_bfloat16* Kl = sm + SM_K_LO;
    __half*        Vf = (__half*)(sm + SM_VF);
    int* toks = (int*)(sm + SM_TOK);

    int g = blockIdx.x, h = blockIdx.y, b = blockIdx.z;
    int tid = threadIdx.x, lane = tid & 31, warp = tid >> 5;

    // ---- load & gather: thread t owns row t/2, 16-float half (t&1) of each tensor ----
    {
        int row = tid >> 1, half = tid & 1;
        int tok = g_sortidx[b * NN + g * GS + row];
        if (half == 0) toks[row] = tok;
        size_t base = (size_t)(b * NN + tok) * C3 + h * DD + half * 16;
        int soff = row * AST + half * 16;
#pragma unroll
        for (int tsel = 0; tsel < 2; tsel++) {      // Q, K: bf16 hi/lo split
            const float4* src = (const float4*)(qkv + base + tsel * CC);
            __nv_bfloat16* dh = (tsel == 0 ? Qh : Kh) + soff;
            __nv_bfloat16* dl = (tsel == 0 ? Ql : Kl) + soff;
#pragma unroll
            for (int i = 0; i < 4; i++) {
                float4 x = src[i];
                __nv_bfloat162 h01 = __floats2bfloat162_rn(x.x, x.y);
                __nv_bfloat162 h23 = __floats2bfloat162_rn(x.z, x.w);
                float2 f01 = __bfloat1622float2(h01);
                float2 f23 = __bfloat1622float2(h23);
                __nv_bfloat162 l01 = __floats2bfloat162_rn(x.x - f01.x, x.y - f01.y);
                __nv_bfloat162 l23 = __floats2bfloat162_rn(x.z - f23.x, x.w - f23.y);
                *(uint2*)(dh + i * 4) = make_uint2(*(uint32_t*)&h01, *(uint32_t*)&h23);
                *(uint2*)(dl + i * 4) = make_uint2(*(uint32_t*)&l01, *(uint32_t*)&l23);
            }
        }
        {                                            // V: single fp16 plane
            const float4* src = (const float4*)(qkv + base + 2 * CC);
            __half* dv = Vf + soff;
#pragma unroll
            for (int i = 0; i < 4; i++) {
                float4 x = src[i];
                __half2 p01 = __floats2half2_rn(x.x, x.y);
                __half2 p23 = __floats2half2_rn(x.z, x.w);
                *(uint2*)(dv + i * 4) = make_uint2(*(uint32_t*)&p01, *(uint32_t*)&p23);
            }
        }
    }
    float scale = __expf(fminf(logit_scale[0], 4.605170185988091f));
    __syncthreads();

    int m0 = warp * 16;
    int l16 = lane & 15;

    uint32_t qh[2][4], ql[2][4];
#pragma unroll
    for (int ks = 0; ks < 2; ks++) {
        ldm_x4(qh[ks], smem_u32(Qh + (m0 + l16) * AST + ks * 16 + (lane >> 4) * 8));
        ldm_x4(ql[ks], smem_u32(Ql + (m0 + l16) * AST + ks * 16 + (lane >> 4) * 8));
    }

    float s[16][4];
#pragma unroll
    for (int nf = 0; nf < 16; nf++)
#pragma unroll
        for (int r = 0; r < 4; r++) s[nf][r] = 0.0f;

#pragma unroll
    for (int p2 = 0; p2 < 8; p2++) {
        int j0 = p2 * 16;
#pragma unroll
        for (int ks = 0; ks < 2; ks++) {
            uint32_t kb[4], kl4[4];
            int krow = j0 + ((lane >> 4) << 3) + (lane & 7);
            int kcol = ks * 16 + ((lane >> 3) & 1) * 8;
            ldm_x4(kb,  smem_u32(Kh + krow * AST + kcol));
            ldm_x4(kl4, smem_u32(Kl + krow * AST + kcol));
            mma_bf16(s[2 * p2],     qh[ks], kb[0],  kb[1]);
            mma_bf16(s[2 * p2],     qh[ks], kl4[0], kl4[1]);
            mma_bf16(s[2 * p2],     ql[ks], kb[0],  kb[1]);
            mma_bf16(s[2 * p2 + 1], qh[ks], kb[2],  kb[3]);
            mma_bf16(s[2 * p2 + 1], qh[ks], kl4[2], kl4[3]);
            mma_bf16(s[2 * p2 + 1], ql[ks], kb[2],  kb[3]);
        }
    }

    float m01 = -3.402823466e38f, m23 = -3.402823466e38f;
#pragma unroll
    for (int nf = 0; nf < 16; nf++) {
#pragma unroll
        for (int r = 0; r < 4; r++) s[nf][r] *= scale;
        m01 = fmaxf(m01, fmaxf(s[nf][0], s[nf][1]));
        m23 = fmaxf(m23, fmaxf(s[nf][2], s[nf][3]));
    }
    m01 = fmaxf(m01, __shfl_xor_sync(0xffffffffu, m01, 1));
    m01 = fmaxf(m01, __shfl_xor_sync(0xffffffffu, m01, 2));
    m23 = fmaxf(m23, __shfl_xor_sync(0xffffffffu, m23, 1));
    m23 = fmaxf(m23, __shfl_xor_sync(0xffffffffu, m23, 2));

    float sum01 = 0.0f, sum23 = 0.0f;
#pragma unroll
    for (int nf = 0; nf < 16; nf++) {
        float e0 = __expf(s[nf][0] - m01);
        float e1 = __expf(s[nf][1] - m01);
        float e2 = __expf(s[nf][2] - m23);
        float e3 = __expf(s[nf][3] - m23);
        s[nf][0] = e0; s[nf][1] = e1; s[nf][2] = e2; s[nf][3] = e3;
        sum01 += e0 + e1;
        sum23 += e2 + e3;
    }
    sum01 += __shfl_xor_sync(0xffffffffu, sum01, 1);
    sum01 += __shfl_xor_sync(0xffffffffu, sum01, 2);
    sum23 += __shfl_xor_sync(0xffffffffu, sum23, 1);
    sum23 += __shfl_xor_sync(0xffffffffu, sum23, 2);

    float o[4][4];
#pragma unroll
    for (int nf = 0; nf < 4; nf++)
#pragma unroll
        for (int r = 0; r < 4; r++) o[nf][r] = 0.0f;

#pragma unroll
    for (int kj = 0; kj < 8; kj++) {
        int f0 = 2 * kj, f1 = 2 * kj + 1;
        uint32_t ph[4];
        ph[0] = packh2(s[f0][0], s[f0][1]);
        ph[1] = packh2(s[f0][2], s[f0][3]);
        ph[2] = packh2(s[f1][0], s[f1][1]);
        ph[3] = packh2(s[f1][2], s[f1][3]);

        int vrow = kj * 16 + l16;
#pragma unroll
        for (int dh2 = 0; dh2 < 2; dh2++) {
            uint32_t vf[4];
            ldm_x4_t(vf, smem_u32(Vf + vrow * AST + dh2 * 16 + ((lane >> 4) << 3)));
            mma_f16(o[2 * dh2],     ph, vf[0], vf[1]);
            mma_f16(o[2 * dh2 + 1], ph, vf[2], vf[3]);
        }
    }

    float inv0 = 1.0f / sum01, inv1 = 1.0f / sum23;
    int r0 = m0 + (lane >> 2);
    int tok0 = toks[r0], tok1 = toks[r0 + 8];
    size_t ob0 = (size_t)(b * NN + tok0) * CC + h * DD + (lane & 3) * 2;
    size_t ob1 = (size_t)(b * NN + tok1) * CC + h * DD + (lane & 3) * 2;
#pragma unroll
    for (int nf = 0; nf < 4; nf++) {
        float v0 = o[nf][0] * inv0, v1 = o[nf][1] * inv0;
        float v2 = o[nf][2] * inv1, v3 = o[nf][3] * inv1;
        __nv_bfloat162 a01 = __floats2bfloat162_rn(v0, v1);
        __nv_bfloat162 a23 = __floats2bfloat162_rn(v2, v3);
        float2 fa = __bfloat1622float2(a01), fb = __bfloat1622float2(a23);
        __nv_bfloat162 b01 = __floats2bfloat162_rn(v0 - fa.x, v1 - fa.y);
        __nv_bfloat162 b23 = __floats2bfloat162_rn(v2 - fb.x, v3 - fb.y);
        *(__nv_bfloat162*)(g_y_hi + ob0 + nf * 8) = a01;
        *(__nv_bfloat162*)(g_y_lo + ob0 + nf * 8) = b01;
        *(__nv_bfloat162*)(g_y_hi + ob1 + nf * 8) = a23;
        *(__nv_bfloat162*)(g_y_lo + ob1 + nf * 8) = b23;
    }
}

// ---------------- 4) projection: bf16x3 MMA, cp.async double-buffered ----------------
#define PST  40
#define PPL  (128 * PST)
#define PSTG (4 * PPL)
#define SMEM_PROJ_BYTES (2 * PSTG * 2)

__global__ void __launch_bounds__(256)
k_proj2(const float* __restrict__ bias, float* __restrict__ out) {
    __nv_bfloat16* sm = (__nv_bfloat16*)dynsm;

    int tid  = threadIdx.x;
    int lane = tid & 31;
    int warp = tid >> 5;
    int row0 = blockIdx.x * 128;
    int col0 = blockIdx.y * 128;
    int m_off = (warp & 3) * 32;
    int n_off = (warp >> 2) * 64;
    int l16 = lane & 15;

    int c0 = tid * 2;
    int rA0 = c0 >> 2, qA0 = (c0 & 3) * 8;
    int rA1 = (c0 + 1) >> 2, qA1 = ((c0 + 1) & 3) * 8;

    const __nv_bfloat16* gA_hi = g_y_hi + (size_t)row0 * CC;
    const __nv_bfloat16* gA_lo = g_y_lo + (size_t)row0 * CC;
    const __nv_bfloat16* gB_hi = g_w_hi + (size_t)col0 * CC;
    const __nv_bfloat16* gB_lo = g_w_lo + (size_t)col0 * CC;

    auto load_stage = [&](int st, int k0) {
        __nv_bfloat16* Ah = sm + st * PSTG;
        __nv_bfloat16* Al = Ah + PPL;
        __nv_bfloat16* Bh = Al + PPL;
        __nv_bfloat16* Bl = Bh + PPL;
        cp16(Ah + rA0 * PST + qA0, gA_hi + (size_t)rA0 * CC + k0 + qA0);
        cp16(Ah + rA1 * PST + qA1, gA_hi + (size_t)rA1 * CC + k0 + qA1);
        cp16(Al + rA0 * PST + qA0, gA_lo + (size_t)rA0 * CC + k0 + qA0);
        cp16(Al + rA1 * PST + qA1, gA_lo + (size_t)rA1 * CC + k0 + qA1);
        cp16(Bh + rA0 * PST + qA0, gB_hi + (size_t)rA0 * CC + k0 + qA0);
        cp16(Bh + rA1 * PST + qA1, gB_hi + (size_t)rA1 * CC + k0 + qA1);
        cp16(Bl + rA0 * PST + qA0, gB_lo + (size_t)rA0 * CC + k0 + qA0);
        cp16(Bl + rA1 * PST + qA1, gB_lo + (size_t)rA1 * CC + k0 + qA1);
        CP_COMMIT();
    };

    float c[2][8][4];
#pragma unroll
    for (int mf = 0; mf < 2; mf++)
#pragma unroll
        for (int nf = 0; nf < 8; nf++)
#pragma unroll
            for (int r = 0; r < 4; r++) c[mf][nf][r] = 0.0f;

    load_stage(0, 0);

    for (int kt = 0; kt < 8; kt++) {
        if (kt + 1 < 8) {
            load_stage((kt + 1) & 1, (kt + 1) * 32);
            CP_WAIT(1);
        } else {
            CP_WAIT(0);
        }
        __syncthreads();

        __nv_bfloat16* Ah = sm + (kt & 1) * PSTG;
        __nv_bfloat16* Al = Ah + PPL;
        __nv_bfloat16* Bh = Al + PPL;
        __nv_bfloat16* Bl = Bh + PPL;

#pragma unroll
        for (int kk = 0; kk < 32; kk += 16) {
            uint32_t bh[8][2], bl[8][2];
#pragma unroll
            for (int np = 0; np < 4; np++) {
                uint32_t t4[4];
                int brow = n_off + np * 16 + ((lane >> 4) << 3) + (lane & 7);
                int bcol = kk + ((lane >> 3) & 1) * 8;
                ldm_x4(t4, smem_u32(Bh + brow * PST + bcol));
                bh[2 * np][0] = t4[0]; bh[2 * np][1] = t4[1];
                bh[2 * np + 1][0] = t4[2]; bh[2 * np + 1][1] = t4[3];
                ldm_x4(t4, smem_u32(Bl + brow * PST + bcol));
                bl[2 * np][0] = t4[0]; bl[2 * np][1] = t4[1];
                bl[2 * np + 1][0] = t4[2]; bl[2 * np + 1][1] = t4[3];
            }
#pragma unroll
            for (int mf = 0; mf < 2; mf++) {
                uint32_t ah[4], al[4];
                int arow = m_off + mf * 16 + l16;
                ldm_x4(ah, smem_u32(Ah + arow * PST + kk + (lane >> 4) * 8));
                ldm_x4(al, smem_u32(Al + arow * PST + kk + (lane >> 4) * 8));
#pragma unroll
                for (int nf = 0; nf < 8; nf++) {
                    mma_bf16(c[mf][nf], ah, bh[nf][0], bh[nf][1]);
                    mma_bf16(c[mf][nf], ah, bl[nf][0], bl[nf][1]);
                    mma_bf16(c[mf][nf], al, bh[nf][0], bh[nf][1]);
                }
            }
        }
        __syncthreads();
    }

#pragma unroll
    for (int mf = 0; mf < 2; mf++) {
#pragma unroll
        for (int nf = 0; nf < 8; nf++) {
            int rg = row0 + m_off + mf * 16 + (lane >> 2);
            int cg = col0 + n_off + nf * 8 + (lane & 3) * 2;
            float b0 = bias[cg], b1 = bias[cg + 1];
            float2* o0 = (float2*)(out + (size_t)rg * CC + cg);
            float2* o1 = (float2*)(out + (size_t)(rg + 8) * CC + cg);
            *o0 = make_float2(c[mf][nf][0] + b0, c[mf][nf][1] + b1);
            *o1 = make_float2(c[mf][nf][2] + b0, c[mf][nf][3] + b1);
        }
    }
}

// ---------------- launch ----------------
extern "C" void kernel_launch(void* const* d_in, const int* in_sizes, int n_in,
                              void* d_out, int out_size) {
    const float* qkv         = (const float*)d_in[0];  // [4,16384,768]
    const float* sim         = (const float*)d_in[1];  // [4,16384,64]
    const float* proj_w      = (const float*)d_in[2];  // [256,256]
    const float* proj_b      = (const float*)d_in[3];  // [256]
    const float* logit_scale = (const float*)d_in[4];  // [1,1]
    float* out = (float*)d_out;

    // 1+2a) fused argmax + histogram + W split
    k_argmax_hist<<<BB * NCH, CHSZ>>>(sim, proj_w);

    // 2b/2c) scan + stable scatter
    k_scan<<<BB, 256>>>();
    k_scatter_par<<<BB * NCH, CHSZ>>>();

    // 3) tensor-core grouped attention (gather + inverse-scatter fused)
    cudaFuncSetAttribute(k_attn_mma, cudaFuncAttributeMaxDynamicSharedMemorySize, SMEM_ATT_BYTES);
    k_attn_mma<<<dim3(NG, HH, BB), 256, SMEM_ATT_BYTES>>>(qkv, logit_scale);

    // 4) projection + bias, double-buffered bf16x3 MMA
    cudaFuncSetAttribute(k_proj2, cudaFuncAttributeMaxDynamicSharedMemorySize, SMEM_PROJ_BYTES);
    k_proj2<<<dim3((BB * NN) / 128, CC / 128), 256, SMEM_PROJ_BYTES>>>(proj_b, out);
}